// round 16
// baseline (speedup 1.0000x reference)
#include <cuda_runtime.h>
#include <cuda_bf16.h>
#include <cstdint>
#include <cstddef>

// ============================================================================
// out = (q_lhs @ q_rhs) / (s_lhs * s_rhs), dynamic per-tensor symmetric int8.
// R16: overlap quantization under the GEMM. One fused 1024-CTA launch:
// CTAs [0,148) first produce quantized data in k-slice order (64 slices x
// 128 items), signaling g_kflag[ks]; ALL CTAs run the validated R8 GEMM tile,
// polling kflag[jn] before loading k-stage jn (poll disabled once all slices
// land). GEMM (tensor-bound, 5% DRAM) overlaps quant (DRAM-bound, 0% tensor).
// ============================================================================

#define MDIM 4096
#define NDIM 4096
#define KDIM 4096

#define NPROD 148                   // producer CTAs (wave-1 resident)
#define ITEMS_PER_SLICE 128         // 64 A-chunks + 64 BT-tiles
#define N_ITEMS (64 * ITEMS_PER_SLICE)   // 8192

// -------------------- device scratch (no allocation allowed) ---------------
__device__ unsigned int g_absmax[2];    // zero-init; reset by last GEMM CTA
__device__ unsigned int g_done;         // finished-CTA ticket, reset likewise
__device__ unsigned int g_kflag[64];    // per-k-slice completion counters
__device__ __nv_bfloat16 g_hA[(size_t)MDIM * KDIM];   // lhs quantized bf16, [M,K]
__device__ __nv_bfloat16 g_hB[(size_t)NDIM * KDIM];   // rhs^T quantized bf16, [N,K]

// -------------------- small helpers -----------------------------------------
__device__ __forceinline__ uint32_t smem_u32(const void* p) {
    uint32_t a;
    asm("{ .reg .u64 t; cvta.to.shared.u64 t, %1; cvt.u32.u64 %0, t; }" : "=r"(a) : "l"(p));
    return a;
}

__device__ __forceinline__ void cp_async16(uint32_t dst, const void* src) {
    asm volatile("cp.async.cg.shared.global [%0], [%1], 16;" :: "r"(dst), "l"(src) : "memory");
}
#define CP_COMMIT() asm volatile("cp.async.commit_group;" ::: "memory")
#define CP_WAIT1()  asm volatile("cp.async.wait_group 1;"  ::: "memory")
#define CP_WAIT0()  asm volatile("cp.async.wait_group 0;"  ::: "memory")

__device__ __forceinline__ void ldmx4(uint32_t& r0, uint32_t& r1, uint32_t& r2, uint32_t& r3,
                                      uint32_t addr) {
    asm volatile("ldmatrix.sync.aligned.m8n8.x4.shared.b16 {%0,%1,%2,%3}, [%4];"
                 : "=r"(r0), "=r"(r1), "=r"(r2), "=r"(r3) : "r"(addr));
}

__device__ __forceinline__ void hmma16816(float* c, const uint32_t* a, const uint32_t* b) {
    asm volatile(
        "mma.sync.aligned.m16n8k16.row.col.f32.bf16.bf16.f32 "
        "{%0,%1,%2,%3}, {%4,%5,%6,%7}, {%8,%9}, {%0,%1,%2,%3};"
        : "+f"(c[0]), "+f"(c[1]), "+f"(c[2]), "+f"(c[3])
        : "r"(a[0]), "r"(a[1]), "r"(a[2]), "r"(a[3]), "r"(b[0]), "r"(b[1]));
}

__device__ __forceinline__ float max4(float4 v) {
    return fmaxf(fmaxf(fabsf(v.x), fabsf(v.y)), fmaxf(fabsf(v.z), fabsf(v.w)));
}

__device__ __forceinline__ float quantf(float x, float s) {
    return fminf(fmaxf(rintf(x * s), -127.0f), 127.0f);
}

__device__ __forceinline__ uint32_t pack2(float a, float b) {
    __nv_bfloat162 t = __floats2bfloat162_rn(a, b);
    return *reinterpret_cast<uint32_t*>(&t);
}

__device__ __forceinline__ void poll_flag(int ks) {
    while (*((volatile unsigned int*)&g_kflag[ks]) < (unsigned)ITEMS_PER_SLICE)
        __nanosleep(64);
}

// ============================================================================
// Kernel 1: fused per-tensor absmax for BOTH tensors, one launch, MLP=8.
// ============================================================================
__global__ void absmax2_kernel(const float4* __restrict__ a,
                               const float4* __restrict__ b, int n4) {
    int half = gridDim.x >> 1;
    int slot = (blockIdx.x >= half) ? 1 : 0;
    const float4* x = slot ? b : a;
    int bid = blockIdx.x - slot * half;
    int stride = half * blockDim.x;

    float m = 0.0f;
    int i = bid * blockDim.x + threadIdx.x;
    for (; i + 7 * stride < n4; i += 8 * stride) {
        float4 v0 = x[i];
        float4 v1 = x[i + stride];
        float4 v2 = x[i + 2 * stride];
        float4 v3 = x[i + 3 * stride];
        float4 v4 = x[i + 4 * stride];
        float4 v5 = x[i + 5 * stride];
        float4 v6 = x[i + 6 * stride];
        float4 v7 = x[i + 7 * stride];
        float m0 = fmaxf(fmaxf(max4(v0), max4(v1)), fmaxf(max4(v2), max4(v3)));
        float m1 = fmaxf(fmaxf(max4(v4), max4(v5)), fmaxf(max4(v6), max4(v7)));
        m = fmaxf(m, fmaxf(m0, m1));
    }
    for (; i < n4; i += stride) m = fmaxf(m, max4(x[i]));

    #pragma unroll
    for (int o = 16; o; o >>= 1) m = fmaxf(m, __shfl_xor_sync(0xFFFFFFFFu, m, o));
    __shared__ float sm[8];
    if ((threadIdx.x & 31) == 0) sm[threadIdx.x >> 5] = m;
    __syncthreads();
    if (threadIdx.x == 0) {
        float bm = sm[0];
        #pragma unroll
        for (int i2 = 1; i2 < 8; i2++) bm = fmaxf(bm, sm[i2]);
        atomicMax(&g_absmax[slot], __float_as_uint(bm));
    }
}

// ============================================================================
// Kernel 2: fused quant-producer + GEMM-consumer.
// ============================================================================
#define TILE_M 128
#define TILE_N 128
#define STAGES 3
#define ST_BYTES 16384
#define SMEM_B_OFF (STAGES * ST_BYTES)
#define SMEM_TOTAL (2 * STAGES * ST_BYTES)
#define NKT (KDIM / 64)                 // 64

__device__ __forceinline__ uint32_t swz_off(int row, int c16) {
    return (uint32_t)(row * 128 + ((c16 ^ (row & 7)) << 4));
}

__device__ __forceinline__ void load_stage_b(uint32_t sb, int tid, int st,
                                             const char* ga, const char* gb, size_t rstride) {
    uint32_t ab = sb + st * ST_BYTES;
    uint32_t bb = sb + SMEM_B_OFF + st * ST_BYTES;
    #pragma unroll
    for (int i = 0; i < 4; i++) {
        int idx = tid + i * 256;
        int row = idx >> 3, c16 = idx & 7;
        cp_async16(ab + swz_off(row, c16), ga + (size_t)row * rstride + c16 * 16);
    }
    #pragma unroll
    for (int i = 0; i < 4; i++) {
        int idx = tid + i * 256;
        int row = idx >> 3, c16 = idx & 7;
        cp_async16(bb + swz_off(row, c16), gb + (size_t)row * rstride + c16 * 16);
    }
}

struct GemmCtx {
    uint32_t sb;
    int tid;
    const char* gA;
    const char* gB;
    int a_row_l, a_chalf, b_row_l, b_chalf, wm, wn;
    int* s_all;       // shared latch: all slices complete
};

template <int ST, bool LAST>
__device__ __forceinline__ void k_iter(const GemmCtx& x, int ks, float c[4][4][4]) {
    const size_t rstride = (size_t)KDIM * 2;
    if (LAST) { CP_WAIT0(); } else { CP_WAIT1(); }
    __syncthreads();

    int jn = ks + STAGES - 1;
    if (jn < NKT) {
        if (!*(x.s_all)) {
            poll_flag(jn);
            if (x.tid == 0 &&
                *((volatile unsigned int*)&g_kflag[NKT - 1]) >= (unsigned)ITEMS_PER_SLICE)
                *(x.s_all) = 1;
        }
        constexpr int ST2 = (ST + 2) % 3;
        load_stage_b(x.sb, x.tid, ST2, x.gA + (size_t)jn * 128, x.gB + (size_t)jn * 128, rstride);
        CP_COMMIT();
    }

    uint32_t ab = x.sb + ST * ST_BYTES;
    uint32_t bb = x.sb + SMEM_B_OFF + ST * ST_BYTES;

    #pragma unroll
    for (int kb = 0; kb < 4; kb++) {
        uint32_t a[4][4];
        uint32_t b[4][2];
        #pragma unroll
        for (int f = 0; f < 4; f++) {
            int row = x.wm * 64 + f * 16 + x.a_row_l;
            ldmx4(a[f][0], a[f][1], a[f][2], a[f][3], ab + swz_off(row, 2 * kb + x.a_chalf));
        }
        #pragma unroll
        for (int p = 0; p < 2; p++) {
            int row = x.wn * 32 + p * 16 + x.b_row_l;
            ldmx4(b[2 * p][0], b[2 * p][1], b[2 * p + 1][0], b[2 * p + 1][1],
                  bb + swz_off(row, 2 * kb + x.b_chalf));
        }
        #pragma unroll
        for (int f = 0; f < 4; f++)
            #pragma unroll
            for (int j = 0; j < 4; j++)
                hmma16816(c[f][j], a[f], b[j]);
    }
}

__global__ void __launch_bounds__(256, 2) fused_kernel(const float* __restrict__ lhs,
                                                       const float* __restrict__ rhs,
                                                       float* __restrict__ out) {
    extern __shared__ char smem[];
    __shared__ int s_all;
    int tid = threadIdx.x;
    int bid = blockIdx.x;

    // ======================= producer phase (CTAs 0..147) ====================
    if (bid < NPROD) {
        float sA = 127.0f / fmaxf(__uint_as_float(g_absmax[0]), 1e-6f);
        float sB = 127.0f / fmaxf(__uint_as_float(g_absmax[1]), 1e-6f);
        float (*tile)[65] = reinterpret_cast<float (*)[65]>(smem);

        for (int g = bid; g < N_ITEMS; g += NPROD) {
            int ks = g >> 7;
            int j  = g & 127;
            if (j < 64) {
                // A-chunk: rows [j*64, j*64+64), cols [ks*64, ks*64+64)
                int r = j * 64 + (tid >> 2);
                int q = tid & 3;
                const float4* src = reinterpret_cast<const float4*>(
                    lhs + (size_t)r * KDIM + ks * 64 + q * 16);
                float4 v0 = src[0], v1 = src[1], v2 = src[2], v3 = src[3];
                uint4 p0, p1;
                p0.x = pack2(quantf(v0.x, sA), quantf(v0.y, sA));
                p0.y = pack2(quantf(v0.z, sA), quantf(v0.w, sA));
                p0.z = pack2(quantf(v1.x, sA), quantf(v1.y, sA));
                p0.w = pack2(quantf(v1.z, sA), quantf(v1.w, sA));
                p1.x = pack2(quantf(v2.x, sA), quantf(v2.y, sA));
                p1.y = pack2(quantf(v2.z, sA), quantf(v2.w, sA));
                p1.z = pack2(quantf(v3.x, sA), quantf(v3.y, sA));
                p1.w = pack2(quantf(v3.z, sA), quantf(v3.w, sA));
                uint4* dst = reinterpret_cast<uint4*>(
                    g_hA + (size_t)r * KDIM + ks * 64 + q * 16);
                dst[0] = p0;
                dst[1] = p1;
            } else {
                // BT tile: rhs [K,N] rows [ks*64..), cols [(j-64)*64..) -> g_hB
                int n0 = (j - 64) * 64;
                int k0 = ks * 64;
                {
                    int row = tid >> 2;
                    int c4  = tid & 3;
                    const float4* src = reinterpret_cast<const float4*>(
                        rhs + (size_t)(k0 + row) * NDIM + n0);
                    #pragma unroll
                    for (int i = 0; i < 4; i++) {
                        float4 v = src[c4 * 4 + i];
                        int c = c4 * 16 + i * 4;
                        tile[row][c + 0] = v.x;
                        tile[row][c + 1] = v.y;
                        tile[row][c + 2] = v.z;
                        tile[row][c + 3] = v.w;
                    }
                }
                __syncthreads();
                {
                    int n  = tid & 63;
                    int kc = tid >> 6;
                    uint32_t packed[8];
                    #pragma unroll
                    for (int i = 0; i < 8; i++)
                        packed[i] = pack2(quantf(tile[kc * 16 + 2 * i][n], sB),
                                          quantf(tile[kc * 16 + 2 * i + 1][n], sB));
                    __nv_bfloat16* dst = g_hB + (size_t)(n0 + n) * KDIM + k0 + kc * 16;
                    uint4* d4 = reinterpret_cast<uint4*>(dst);
                    d4[0] = make_uint4(packed[0], packed[1], packed[2], packed[3]);
                    d4[1] = make_uint4(packed[4], packed[5], packed[6], packed[7]);
                }
            }
            __threadfence();
            __syncthreads();
            if (tid == 0) atomicAdd(&g_kflag[ks], 1u);
        }
    }

    // ======================= consumer phase (all 1024 CTAs) ==================
    GemmCtx x;
    x.sb  = smem_u32(smem);
    x.tid = tid;
    int wid  = tid >> 5;
    int lane = tid & 31;
    x.wm = wid >> 2;
    x.wn = wid & 3;
    x.s_all = &s_all;
    int m0 = (bid >> 5) * TILE_M;
    int n0 = (bid & 31) * TILE_N;

    x.gA = (const char*)g_hA + (size_t)m0 * KDIM * 2;
    x.gB = (const char*)g_hB + (size_t)n0 * KDIM * 2;
    const size_t rstride = (size_t)KDIM * 2;

    float c[4][4][4];
    #pragma unroll
    for (int f = 0; f < 4; f++)
        #pragma unroll
        for (int j = 0; j < 4; j++)
            #pragma unroll
            for (int q = 0; q < 4; q++) c[f][j][q] = 0.0f;

    x.a_row_l = lane & 15;
    x.a_chalf = lane >> 4;
    x.b_row_l = ((lane >> 4) << 3) + (lane & 7);
    x.b_chalf = (lane >> 3) & 1;

    if (tid == 0) s_all = 0;
    __syncthreads();

    // prologue: slices 0 and 1 must be ready
    poll_flag(0);
    poll_flag(1);
    #pragma unroll
    for (int j = 0; j < STAGES - 1; j++) {
        load_stage_b(x.sb, x.tid, j, x.gA + (size_t)j * 128, x.gB + (size_t)j * 128, rstride);
        CP_COMMIT();
    }

    int ks = 0;
    #pragma unroll 1
    for (int t = 0; t < 21; t++) {
        k_iter<0, false>(x, ks + 0, c);
        k_iter<1, false>(x, ks + 1, c);
        k_iter<2, false>(x, ks + 2, c);
        ks += 3;
    }
    k_iter<0, true>(x, 63, c);

    float bl = fmaxf(__uint_as_float(g_absmax[0]), 1e-6f);
    float br = fmaxf(__uint_as_float(g_absmax[1]), 1e-6f);
    float factor = bl * br * (1.0f / (127.0f * 127.0f));

    int g   = lane >> 2;
    int tig = lane & 3;
    #pragma unroll
    for (int f = 0; f < 4; f++) {
        int row0 = m0 + x.wm * 64 + f * 16 + g;
        #pragma unroll
        for (int j = 0; j < 4; j++) {
            int col = n0 + x.wn * 32 + j * 8 + tig * 2;
            float2 v0, v1;
            v0.x = c[f][j][0] * factor;
            v0.y = c[f][j][1] * factor;
            v1.x = c[f][j][2] * factor;
            v1.y = c[f][j][3] * factor;
            *reinterpret_cast<float2*>(out + (size_t)row0 * NDIM + col)       = v0;
            *reinterpret_cast<float2*>(out + (size_t)(row0 + 8) * NDIM + col) = v1;
        }
    }

    // Last CTA resets scratch state for the next graph replay.
    __syncthreads();
    if (tid == 0) {
        __threadfence();
        unsigned int ticket = atomicInc(&g_done, 0xFFFFFFFFu);
        if (ticket == gridDim.x - 1) {
            g_absmax[0] = 0u;
            g_absmax[1] = 0u;
            #pragma unroll 1
            for (int k = 0; k < 64; k++) g_kflag[k] = 0u;
            g_done = 0u;
            __threadfence();
        }
    }
}

// ============================================================================
// Launch
// ============================================================================
extern "C" void kernel_launch(void* const* d_in, const int* in_sizes, int n_in,
                              void* d_out, int out_size) {
    const float* lhs = (const float*)d_in[0];
    const float* rhs = (const float*)d_in[1];
    float* out = (float*)d_out;

    cudaFuncSetAttribute(fused_kernel, cudaFuncAttributeMaxDynamicSharedMemorySize, SMEM_TOTAL);

    const int n4 = (MDIM * KDIM) / 4;
    absmax2_kernel<<<1216, 256>>>((const float4*)lhs, (const float4*)rhs, n4);

    fused_kernel<<<1024, 256, SMEM_TOTAL>>>(lhs, rhs, out);
}

// round 17
// speedup vs baseline: 1.4554x; 1.4554x over previous
#include <cuda_runtime.h>
#include <cuda_bf16.h>
#include <cstdint>
#include <cstddef>

// ============================================================================
// out = (q_lhs @ q_rhs) / (s_lhs * s_rhs), dynamic per-tensor symmetric int8.
// R17 (final): exact R13 configuration — measured best (344.5us).
//   absmax2 (fused both tensors, MLP=4)           ~24us
//   quantAB (merged quantA 16B-stores + quantBT)  ~33us
//   qgemm_hmma (R8 core: 128x128, 256thr, 2 CTA/SM, 3-stage cp.async,
//               static stage offsets)             ~285us @ 79.6% tensor
// Engine rationale: tcgen05 rejected by plain-sm_103 ptxas; legacy bf16 HMMA
// measured 2x legacy IMMA; quantized ints are exact in bf16 (fp32 accum),
// rel_err 7.4e-8. Scheduling experiments (split-K, work-stealing, grid-barrier
// fusion, producer-consumer overlap) all regressed — HW scheduler wins.
// ============================================================================

#define MDIM 4096
#define NDIM 4096
#define KDIM 4096

#define QA_BLOCKS 2048
#define QBT_BLOCKS (64 * 64)                 // 4096 tiles of 64x64
#define QAB_GRID  (QA_BLOCKS + QBT_BLOCKS)   // 6144

// -------------------- device scratch (no allocation allowed) ---------------
__device__ unsigned int g_absmax[2];    // zero-init; reset by last GEMM CTA
__device__ unsigned int g_done;         // finished-CTA ticket, reset likewise
__device__ __nv_bfloat16 g_hA[(size_t)MDIM * KDIM];   // lhs quantized bf16, [M,K]
__device__ __nv_bfloat16 g_hB[(size_t)NDIM * KDIM];   // rhs^T quantized bf16, [N,K]

// -------------------- small helpers -----------------------------------------
__device__ __forceinline__ uint32_t smem_u32(const void* p) {
    uint32_t a;
    asm("{ .reg .u64 t; cvta.to.shared.u64 t, %1; cvt.u32.u64 %0, t; }" : "=r"(a) : "l"(p));
    return a;
}

__device__ __forceinline__ void cp_async16(uint32_t dst, const void* src) {
    asm volatile("cp.async.cg.shared.global [%0], [%1], 16;" :: "r"(dst), "l"(src) : "memory");
}
#define CP_COMMIT() asm volatile("cp.async.commit_group;" ::: "memory")
#define CP_WAIT1()  asm volatile("cp.async.wait_group 1;"  ::: "memory")
#define CP_WAIT0()  asm volatile("cp.async.wait_group 0;"  ::: "memory")

__device__ __forceinline__ void ldmx4(uint32_t& r0, uint32_t& r1, uint32_t& r2, uint32_t& r3,
                                      uint32_t addr) {
    asm volatile("ldmatrix.sync.aligned.m8n8.x4.shared.b16 {%0,%1,%2,%3}, [%4];"
                 : "=r"(r0), "=r"(r1), "=r"(r2), "=r"(r3) : "r"(addr));
}

__device__ __forceinline__ void hmma16816(float* c, const uint32_t* a, const uint32_t* b) {
    asm volatile(
        "mma.sync.aligned.m16n8k16.row.col.f32.bf16.bf16.f32 "
        "{%0,%1,%2,%3}, {%4,%5,%6,%7}, {%8,%9}, {%0,%1,%2,%3};"
        : "+f"(c[0]), "+f"(c[1]), "+f"(c[2]), "+f"(c[3])
        : "r"(a[0]), "r"(a[1]), "r"(a[2]), "r"(a[3]), "r"(b[0]), "r"(b[1]));
}

__device__ __forceinline__ float max4(float4 v) {
    return fmaxf(fmaxf(fabsf(v.x), fabsf(v.y)), fmaxf(fabsf(v.z), fabsf(v.w)));
}

__device__ __forceinline__ float quantf(float x, float s) {
    return fminf(fmaxf(rintf(x * s), -127.0f), 127.0f);
}

// ============================================================================
// Kernel 1: fused per-tensor absmax for BOTH tensors, one launch, MLP=4.
// ============================================================================
__global__ void absmax2_kernel(const float4* __restrict__ a,
                               const float4* __restrict__ b, int n4) {
    int half = gridDim.x >> 1;
    int slot = (blockIdx.x >= half) ? 1 : 0;
    const float4* x = slot ? b : a;
    int bid = blockIdx.x - slot * half;
    int stride = half * blockDim.x;

    float m = 0.0f;
    int i = bid * blockDim.x + threadIdx.x;
    for (; i + 3 * stride < n4; i += 4 * stride) {
        float4 v0 = x[i];
        float4 v1 = x[i + stride];
        float4 v2 = x[i + 2 * stride];
        float4 v3 = x[i + 3 * stride];
        m = fmaxf(m, fmaxf(fmaxf(max4(v0), max4(v1)), fmaxf(max4(v2), max4(v3))));
    }
    for (; i < n4; i += stride) m = fmaxf(m, max4(x[i]));

    #pragma unroll
    for (int o = 16; o; o >>= 1) m = fmaxf(m, __shfl_xor_sync(0xFFFFFFFFu, m, o));
    __shared__ float sm[8];
    if ((threadIdx.x & 31) == 0) sm[threadIdx.x >> 5] = m;
    __syncthreads();
    if (threadIdx.x == 0) {
        float bm = sm[0];
        #pragma unroll
        for (int i2 = 1; i2 < 8; i2++) bm = fmaxf(bm, sm[i2]);
        atomicMax(&g_absmax[slot], __float_as_uint(bm));
    }
}

// ============================================================================
// Kernel 2 (merged): quantA + quantBT in one launch (validated R13).
// Blocks [0, QA_BLOCKS): lhs -> g_hA. 8 floats/thread, single 16B store,
// reversed traversal (L2 reuse of absmax tail).
// Blocks [QA_BLOCKS, QAB_GRID): rhs 64x64 tile transpose -> g_hB,
// reversed tile mapping, conflict-free smem phases, 2x16B stores.
// ============================================================================
__global__ void __launch_bounds__(256) quantAB_kernel(const float* __restrict__ lhs,
                                                      const float* __restrict__ rhs) {
    if (blockIdx.x < QA_BLOCKS) {
        const int n8 = (MDIM * KDIM) / 8;                 // 2097152
        const int stride = QA_BLOCKS * 256;               // 524288
        float bound = fmaxf(__uint_as_float(g_absmax[0]), 1e-6f);
        float s = 127.0f / bound;
        const float4* in = reinterpret_cast<const float4*>(lhs);
        uint4* outv = reinterpret_cast<uint4*>(g_hA);

        int i = n8 - 1 - (int)(blockIdx.x * 256 + threadIdx.x);
        for (; i - stride >= 0; i -= 2 * stride) {
            float4 a0 = in[2 * i];
            float4 a1 = in[2 * i + 1];
            float4 b0 = in[2 * (i - stride)];
            float4 b1 = in[2 * (i - stride) + 1];
            uint4 pa, pb;
            __nv_bfloat162 t;
            t = __floats2bfloat162_rn(quantf(a0.x, s), quantf(a0.y, s)); pa.x = *(uint32_t*)&t;
            t = __floats2bfloat162_rn(quantf(a0.z, s), quantf(a0.w, s)); pa.y = *(uint32_t*)&t;
            t = __floats2bfloat162_rn(quantf(a1.x, s), quantf(a1.y, s)); pa.z = *(uint32_t*)&t;
            t = __floats2bfloat162_rn(quantf(a1.z, s), quantf(a1.w, s)); pa.w = *(uint32_t*)&t;
            t = __floats2bfloat162_rn(quantf(b0.x, s), quantf(b0.y, s)); pb.x = *(uint32_t*)&t;
            t = __floats2bfloat162_rn(quantf(b0.z, s), quantf(b0.w, s)); pb.y = *(uint32_t*)&t;
            t = __floats2bfloat162_rn(quantf(b1.x, s), quantf(b1.y, s)); pb.z = *(uint32_t*)&t;
            t = __floats2bfloat162_rn(quantf(b1.z, s), quantf(b1.w, s)); pb.w = *(uint32_t*)&t;
            outv[i] = pa;
            outv[i - stride] = pb;
        }
        if (i >= 0) {
            float4 a0 = in[2 * i];
            float4 a1 = in[2 * i + 1];
            uint4 pa;
            __nv_bfloat162 t;
            t = __floats2bfloat162_rn(quantf(a0.x, s), quantf(a0.y, s)); pa.x = *(uint32_t*)&t;
            t = __floats2bfloat162_rn(quantf(a0.z, s), quantf(a0.w, s)); pa.y = *(uint32_t*)&t;
            t = __floats2bfloat162_rn(quantf(a1.x, s), quantf(a1.y, s)); pa.z = *(uint32_t*)&t;
            t = __floats2bfloat162_rn(quantf(a1.z, s), quantf(a1.w, s)); pa.w = *(uint32_t*)&t;
            outv[i] = pa;
        }
    } else {
        __shared__ float tile[64][65];
        int t64 = (int)blockIdx.x - QA_BLOCKS;            // 0..4095
        int bx = 63 - (t64 & 63);                         // reversed mapping
        int by = 63 - (t64 >> 6);
        int n0 = bx * 64;
        int k0 = by * 64;
        int tid = threadIdx.x;
        float bound = fmaxf(__uint_as_float(g_absmax[1]), 1e-6f);
        float s = 127.0f / bound;

        {
            int row = tid >> 2;
            int c4  = tid & 3;
            const float4* src = reinterpret_cast<const float4*>(
                rhs + (size_t)(k0 + row) * NDIM + n0);
            #pragma unroll
            for (int i = 0; i < 4; i++) {
                float4 v = src[c4 * 4 + i];
                int c = c4 * 16 + i * 4;
                tile[row][c + 0] = v.x;
                tile[row][c + 1] = v.y;
                tile[row][c + 2] = v.z;
                tile[row][c + 3] = v.w;
            }
        }
        __syncthreads();

        {
            int n  = tid & 63;
            int kc = tid >> 6;
            uint32_t packed[8];
            #pragma unroll
            for (int i = 0; i < 8; i++) {
                __nv_bfloat162 p = __floats2bfloat162_rn(
                    quantf(tile[kc * 16 + 2 * i][n], s),
                    quantf(tile[kc * 16 + 2 * i + 1][n], s));
                packed[i] = *reinterpret_cast<uint32_t*>(&p);
            }
            __nv_bfloat16* dst = g_hB + (size_t)(n0 + n) * KDIM + k0 + kc * 16;
            uint4* d4 = reinterpret_cast<uint4*>(dst);
            d4[0] = make_uint4(packed[0], packed[1], packed[2], packed[3]);
            d4[1] = make_uint4(packed[4], packed[5], packed[6], packed[7]);
        }
    }
}

// ============================================================================
// Kernel 3: bf16 HMMA GEMM (R8 core, validated). CTA tile 128x128, K-stage 64,
// 3-stage cp.async pipe, 2 CTAs/SM, static stage offsets via unroll-by-3.
// ============================================================================
#define TILE_M 128
#define TILE_N 128
#define STAGES 3
#define ST_BYTES 16384
#define SMEM_B_OFF (STAGES * ST_BYTES)
#define SMEM_TOTAL (2 * STAGES * ST_BYTES)
#define NKT (KDIM / 64)                 // 64

__device__ __forceinline__ uint32_t swz_off(int row, int c16) {
    return (uint32_t)(row * 128 + ((c16 ^ (row & 7)) << 4));
}

__device__ __forceinline__ void load_stage_b(uint32_t sb, int tid, int st,
                                             const char* ga, const char* gb, size_t rstride) {
    uint32_t ab = sb + st * ST_BYTES;
    uint32_t bb = sb + SMEM_B_OFF + st * ST_BYTES;
    #pragma unroll
    for (int i = 0; i < 4; i++) {
        int idx = tid + i * 256;
        int row = idx >> 3, c16 = idx & 7;
        cp_async16(ab + swz_off(row, c16), ga + (size_t)row * rstride + c16 * 16);
    }
    #pragma unroll
    for (int i = 0; i < 4; i++) {
        int idx = tid + i * 256;
        int row = idx >> 3, c16 = idx & 7;
        cp_async16(bb + swz_off(row, c16), gb + (size_t)row * rstride + c16 * 16);
    }
}

struct GemmCtx {
    uint32_t sb;
    int tid;
    const char* gA;
    const char* gB;
    int a_row_l, a_chalf, b_row_l, b_chalf, wm, wn;
};

template <int ST, bool LAST>
__device__ __forceinline__ void k_iter(const GemmCtx& x, int ks, float c[4][4][4]) {
    const size_t rstride = (size_t)KDIM * 2;
    if (LAST) { CP_WAIT0(); } else { CP_WAIT1(); }
    __syncthreads();

    int jn = ks + STAGES - 1;
    if (jn < NKT) {
        constexpr int ST2 = (ST + 2) % 3;
        load_stage_b(x.sb, x.tid, ST2, x.gA + (size_t)jn * 128, x.gB + (size_t)jn * 128, rstride);
        CP_COMMIT();
    }

    uint32_t ab = x.sb + ST * ST_BYTES;
    uint32_t bb = x.sb + SMEM_B_OFF + ST * ST_BYTES;

    #pragma unroll
    for (int kb = 0; kb < 4; kb++) {
        uint32_t a[4][4];
        uint32_t b[4][2];
        #pragma unroll
        for (int f = 0; f < 4; f++) {
            int row = x.wm * 64 + f * 16 + x.a_row_l;
            ldmx4(a[f][0], a[f][1], a[f][2], a[f][3], ab + swz_off(row, 2 * kb + x.a_chalf));
        }
        #pragma unroll
        for (int p = 0; p < 2; p++) {
            int row = x.wn * 32 + p * 16 + x.b_row_l;
            ldmx4(b[2 * p][0], b[2 * p][1], b[2 * p + 1][0], b[2 * p + 1][1],
                  bb + swz_off(row, 2 * kb + x.b_chalf));
        }
        #pragma unroll
        for (int f = 0; f < 4; f++)
            #pragma unroll
            for (int j = 0; j < 4; j++)
                hmma16816(c[f][j], a[f], b[j]);
    }
}

__global__ void __launch_bounds__(256, 2) qgemm_hmma(float* __restrict__ out) {
    extern __shared__ char smem[];
    GemmCtx x;
    x.sb  = smem_u32(smem);
    x.tid = threadIdx.x;
    int wid  = x.tid >> 5;
    int lane = x.tid & 31;
    x.wm = wid >> 2;
    x.wn = wid & 3;
    int m0 = blockIdx.y * TILE_M;
    int n0 = blockIdx.x * TILE_N;

    x.gA = (const char*)g_hA + (size_t)m0 * KDIM * 2;
    x.gB = (const char*)g_hB + (size_t)n0 * KDIM * 2;
    const size_t rstride = (size_t)KDIM * 2;

    float c[4][4][4];
    #pragma unroll
    for (int f = 0; f < 4; f++)
        #pragma unroll
        for (int j = 0; j < 4; j++)
            #pragma unroll
            for (int q = 0; q < 4; q++) c[f][j][q] = 0.0f;

    x.a_row_l = lane & 15;
    x.a_chalf = lane >> 4;
    x.b_row_l = ((lane >> 4) << 3) + (lane & 7);
    x.b_chalf = (lane >> 3) & 1;

    #pragma unroll
    for (int j = 0; j < STAGES - 1; j++) {
        load_stage_b(x.sb, x.tid, j, x.gA + (size_t)j * 128, x.gB + (size_t)j * 128, rstride);
        CP_COMMIT();
    }

    int ks = 0;
    #pragma unroll 1
    for (int t = 0; t < 21; t++) {
        k_iter<0, false>(x, ks + 0, c);
        k_iter<1, false>(x, ks + 1, c);
        k_iter<2, false>(x, ks + 2, c);
        ks += 3;
    }
    k_iter<0, true>(x, 63, c);

    float bl = fmaxf(__uint_as_float(g_absmax[0]), 1e-6f);
    float br = fmaxf(__uint_as_float(g_absmax[1]), 1e-6f);
    float factor = bl * br * (1.0f / (127.0f * 127.0f));

    int g   = lane >> 2;
    int tig = lane & 3;
    #pragma unroll
    for (int f = 0; f < 4; f++) {
        int row0 = m0 + x.wm * 64 + f * 16 + g;
        #pragma unroll
        for (int j = 0; j < 4; j++) {
            int col = n0 + x.wn * 32 + j * 8 + tig * 2;
            float2 v0, v1;
            v0.x = c[f][j][0] * factor;
            v0.y = c[f][j][1] * factor;
            v1.x = c[f][j][2] * factor;
            v1.y = c[f][j][3] * factor;
            *reinterpret_cast<float2*>(out + (size_t)row0 * NDIM + col)       = v0;
            *reinterpret_cast<float2*>(out + (size_t)(row0 + 8) * NDIM + col) = v1;
        }
    }

    // Last CTA resets scratch state for the next graph replay.
    __syncthreads();
    if (x.tid == 0) {
        __threadfence();
        unsigned int ticket = atomicInc(&g_done, 0xFFFFFFFFu);
        if (ticket == gridDim.x * gridDim.y - 1) {
            g_absmax[0] = 0u;
            g_absmax[1] = 0u;
            g_done = 0u;
            __threadfence();
        }
    }
}

// ============================================================================
// Launch
// ============================================================================
extern "C" void kernel_launch(void* const* d_in, const int* in_sizes, int n_in,
                              void* d_out, int out_size) {
    const float* lhs = (const float*)d_in[0];
    const float* rhs = (const float*)d_in[1];
    float* out = (float*)d_out;

    cudaFuncSetAttribute(qgemm_hmma, cudaFuncAttributeMaxDynamicSharedMemorySize, SMEM_TOTAL);

    const int n4 = (MDIM * KDIM) / 4;
    absmax2_kernel<<<1216, 256>>>((const float4*)lhs, (const float4*)rhs, n4);

    quantAB_kernel<<<QAB_GRID, 256>>>(lhs, rhs);

    dim3 ggrid(NDIM / TILE_N, MDIM / TILE_M);   // (32, 32)
    qgemm_hmma<<<ggrid, 256, SMEM_TOTAL>>>(out);
}